// round 16
// baseline (speedup 1.0000x reference)
#include <cuda_runtime.h>
#include <cuda_fp16.h>
#include <cstdint>

#define NH   12
#define DHD  64
#define NSEQ 1024
#define DM   768
#define NTB  16
#define NS   16384   // NTB * NSEQ tokens

// ---------------------------------------------------------------------------
// Scratch (static device globals; no runtime allocation allowed)
// ---------------------------------------------------------------------------
__device__ __align__(256) __half g_q[(size_t)NTB * NH * NSEQ * DHD];   // h(0.125*q)
__device__ __align__(256) __half g_k[(size_t)NTB * NH * NSEQ * DHD];   // h(k)
__device__ __align__(256) __half g_v[(size_t)NTB * NH * NSEQ * DHD];   // h(v)
__device__ __align__(256) __half g_ctx[(size_t)NS * DM];               // h(ctx)
__device__ __align__(256) __half g_xc[(size_t)NS * DM];                // h(x)
__device__ __align__(256) __half g_wqc[(size_t)DM * DM];
__device__ __align__(256) __half g_wkc[(size_t)DM * DM];
__device__ __align__(256) __half g_wvc[(size_t)DM * DM];
__device__ __align__(256) __half g_woc[(size_t)DM * DM];

// ---------------------------------------------------------------------------
// Helpers
// ---------------------------------------------------------------------------
__device__ __forceinline__ uint32_t smem_u32(const void* p) {
    uint32_t a;
    asm("{ .reg .u64 t; cvta.to.shared.u64 t, %1; cvt.u32.u64 %0, t; }" : "=r"(a) : "l"(p));
    return a;
}

__device__ __forceinline__ void cp16(uint32_t dst, const void* src) {
    asm volatile("cp.async.cg.shared.global [%0], [%1], 16;" :: "r"(dst), "l"(src) : "memory");
}
#define CP_COMMIT() asm volatile("cp.async.commit_group;" ::: "memory")
#define CP_WAIT(n)  asm volatile("cp.async.wait_group %0;" :: "n"(n) : "memory")

// fp16 MMA, fp32 accumulate: D(16x8) += A(16x16) * B(16x8)
__device__ __forceinline__ void mma16(float& c0, float& c1, float& c2, float& c3,
                                      unsigned a0, unsigned a1, unsigned a2, unsigned a3,
                                      unsigned b0, unsigned b1) {
    asm volatile(
        "mma.sync.aligned.m16n8k16.row.col.f32.f16.f16.f32 "
        "{%0,%1,%2,%3},{%4,%5,%6,%7},{%8,%9},{%0,%1,%2,%3};"
        : "+f"(c0), "+f"(c1), "+f"(c2), "+f"(c3)
        : "r"(a0), "r"(a1), "r"(a2), "r"(a3), "r"(b0), "r"(b1));
}

// ldmatrix x4 (non-trans / trans) b16
__device__ __forceinline__ void ldmx4(unsigned& r0, unsigned& r1, unsigned& r2, unsigned& r3,
                                      uint32_t addr) {
    asm volatile("ldmatrix.sync.aligned.m8n8.x4.shared.b16 {%0,%1,%2,%3}, [%4];"
                 : "=r"(r0), "=r"(r1), "=r"(r2), "=r"(r3) : "r"(addr));
}
__device__ __forceinline__ void ldmx4t(unsigned& r0, unsigned& r1, unsigned& r2, unsigned& r3,
                                       uint32_t addr) {
    asm volatile("ldmatrix.sync.aligned.m8n8.x4.trans.shared.b16 {%0,%1,%2,%3}, [%4];"
                 : "=r"(r0), "=r"(r1), "=r"(r2), "=r"(r3) : "r"(addr));
}

__device__ __forceinline__ unsigned packh2(float a, float b) {
    __half2 h = __floats2half2_rn(a, b);
    return *reinterpret_cast<unsigned*>(&h);
}

// ---------------------------------------------------------------------------
// Fused fp16 pre-convert: one launch covers x + the 4 weight matrices
// ---------------------------------------------------------------------------
#define NX4 ((NS * DM) / 4)
#define NW4 ((DM * DM) / 4)
#define NCVT4 (NX4 + 4 * NW4)

__global__ __launch_bounds__(256) void cvt_all_k(const float* __restrict__ x,
                                                 const float* __restrict__ Wq,
                                                 const float* __restrict__ Wk,
                                                 const float* __restrict__ Wv,
                                                 const float* __restrict__ Wo) {
    int i = blockIdx.x * blockDim.x + threadIdx.x;
    if (i >= NCVT4) return;
    const float* s;
    __half* d;
    int j;
    if (i < NX4) { s = x; d = g_xc; j = i; }
    else {
        j = i - NX4;
        const int w = j / NW4;
        j -= w * NW4;
        s = (w == 0) ? Wq : (w == 1) ? Wk : (w == 2) ? Wv : Wo;
        d = (w == 0) ? g_wqc : (w == 1) ? g_wkc : (w == 2) ? g_wvc : g_woc;
    }
    float4 v = reinterpret_cast<const float4*>(s)[j];
    __half2 h0 = __floats2half2_rn(v.x, v.y);
    __half2 h1 = __floats2half2_rn(v.z, v.w);
    uint2 pk;
    pk.x = *reinterpret_cast<unsigned*>(&h0);
    pk.y = *reinterpret_cast<unsigned*>(&h1);
    reinterpret_cast<uint2*>(d)[j] = pk;
}

// ---------------------------------------------------------------------------
// fp16 HMMA GEMM: out[s,c] = sum_k A[s,k]*W[c,k] + bias[c]
// CTA 128x128, 256 thr = 8 warps (2m x 4n), WARP TILE 64x32 (acc 64 regs).
// ~105 regs/thr -> 2 CTAs of 256 thr = 16 warps/SM (R15 was latency-bound at
// ~10 warps/SM with the 64x64 tile's 166 regs).  BK=64, 2-stage cp.async,
// one sync/iter, all fragments via ldmatrix.x4.
// mode: 0 = head-split q (x0.125), 1 = head-split k/v, 2 = flat fp32 out
// ---------------------------------------------------------------------------
#define GBM 128
#define GBN 128
#define GSTR 72
#define GA_H (GBM * GSTR)                   // 9216 halves
#define GSTG_H (2 * GA_H)                   // 18432 halves (A + B)
#define GSMEM_B (2 * GSTG_H * 2)            // 73728 bytes
#define GKIT (DM / 64)                      // 12

__device__ __forceinline__ void gemm_body(const __half* __restrict__ A,
                                          const __half* __restrict__ W,
                                          const float* __restrict__ bias,
                                          void* __restrict__ dstp, int mode) {
    extern __shared__ __half smh[];
    const uint32_t smb = smem_u32(smh);
    const int tid  = threadIdx.x;
    const int lane = tid & 31, wid = tid >> 5;
    const int wm = (wid & 1) * 64;          // 2 m-warps
    const int wn = (wid >> 1) * 32;         // 4 n-warps
    const int row0 = blockIdx.x * GBM, col0 = blockIdx.y * GBN;
    const int lr = lane >> 2, lc = lane & 3;

    // ldmatrix lane-address components
    const int m8 = lane >> 3, rr = lane & 7;
    const int a_row = ((m8 & 1) << 3) + rr;   // A: row offset, col += ((m8>>1)<<3)
    const int a_col = (m8 >> 1) << 3;
    const int b_row = ((m8 >> 1) << 3) + rr;  // B: n-row offset, col += ((m8&1)<<3)
    const int b_col = (m8 & 1) << 3;

    float acc[4][4][4];
#pragma unroll
    for (int i = 0; i < 4; i++)
#pragma unroll
        for (int j = 0; j < 4; j++)
#pragma unroll
            for (int e = 0; e < 4; e++) acc[i][j][e] = 0.f;

    // prefetch one stage: A 1024 + B 1024 chunks of 16B (8 halves), 4+4/thr
    auto prefetch = [&](int s, int kk) {
        const uint32_t ab = smb + (uint32_t)(s * GSTG_H) * 2u;
        const uint32_t bb = ab + (uint32_t)GA_H * 2u;
#pragma unroll
        for (int u = tid; u < 1024; u += 256) {
            const int row = u >> 3, c = (u & 7) << 3;
            cp16(ab + (uint32_t)(row * GSTR + c) * 2u,
                 A + (size_t)(row0 + row) * DM + kk + c);
        }
#pragma unroll
        for (int u = tid; u < 1024; u += 256) {
            const int row = u >> 3, c = (u & 7) << 3;
            cp16(bb + (uint32_t)(row * GSTR + c) * 2u,
                 W + (size_t)(col0 + row) * DM + kk + c);
        }
    };

    prefetch(0, 0);
    CP_COMMIT();

    for (int it = 0; it < GKIT; it++) {
        const int s = it & 1;
        CP_WAIT(0);
        __syncthreads();
        if (it + 1 < GKIT) {
            prefetch(s ^ 1, (it + 1) * 64);
            CP_COMMIT();
        }

        const uint32_t abase = smb + (uint32_t)(s * GSTG_H) * 2u;
        const uint32_t bbase = abase + (uint32_t)GA_H * 2u;
#pragma unroll
        for (int ks = 0; ks < 4; ks++) {
            const int kb = ks * 16;
            unsigned af[4][4];
#pragma unroll
            for (int mi = 0; mi < 4; mi++)
                ldmx4(af[mi][0], af[mi][1], af[mi][2], af[mi][3],
                      abase + (uint32_t)((wm + mi * 16 + a_row) * GSTR + kb + a_col) * 2u);
            unsigned bf[4][2];
#pragma unroll
            for (int ni2 = 0; ni2 < 2; ni2++)
                ldmx4(bf[2 * ni2][0], bf[2 * ni2][1], bf[2 * ni2 + 1][0], bf[2 * ni2 + 1][1],
                      bbase + (uint32_t)((wn + ni2 * 16 + b_row) * GSTR + kb + b_col) * 2u);
#pragma unroll
            for (int mi = 0; mi < 4; mi++)
#pragma unroll
                for (int ni = 0; ni < 4; ni++)
                    mma16(acc[mi][ni][0], acc[mi][ni][1], acc[mi][ni][2], acc[mi][ni][3],
                          af[mi][0], af[mi][1], af[mi][2], af[mi][3],
                          bf[ni][0], bf[ni][1]);
        }
    }

    // epilogue
#pragma unroll
    for (int mi = 0; mi < 4; mi++)
#pragma unroll
        for (int ni = 0; ni < 4; ni++)
#pragma unroll
            for (int eh = 0; eh < 2; eh++) {
                const int gr = row0 + wm + mi * 16 + lr + (eh << 3);
                const int gc = col0 + wn + ni * 8 + (lc << 1);
                float v0 = acc[mi][ni][eh * 2]     + __ldg(bias + gc);
                float v1 = acc[mi][ni][eh * 2 + 1] + __ldg(bias + gc + 1);
                if (mode == 2) {
                    float* dst = (float*)dstp;
                    *reinterpret_cast<float2*>(dst + (size_t)gr * DM + gc) =
                        make_float2(v0, v1);
                } else {
                    if (mode == 0) { v0 *= 0.125f; v1 *= 0.125f; }
                    __half* dst = (__half*)dstp;
                    const int tb = gr >> 10, n = gr & 1023;
                    const int h = gc >> 6, d = gc & 63;
                    __half2 hv = __floats2half2_rn(v0, v1);
                    *reinterpret_cast<__half2*>(
                        dst + (((size_t)(tb * NH + h)) * NSEQ + n) * DHD + d) = hv;
                }
            }
}

__global__ __launch_bounds__(256) void gemm_qkv_k(const float* __restrict__ bq,
                                                  const float* __restrict__ bk,
                                                  const float* __restrict__ bv) {
    const int z = blockIdx.z;
    const __half* W = (z == 0) ? g_wqc : (z == 1) ? g_wkc : g_wvc;
    const float* b = (z == 0) ? bq : (z == 1) ? bk : bv;
    __half* dst = (z == 0) ? g_q : (z == 1) ? g_k : g_v;
    gemm_body(g_xc, W, b, dst, (z == 0) ? 0 : 1);
}

__global__ __launch_bounds__(256) void gemm_out_k(const float* __restrict__ bo,
                                                  float* __restrict__ out) {
    gemm_body(g_ctx, g_woc, bo, out, 2);
}

// ---------------------------------------------------------------------------
// Attention (fp16): per (tb,h), 1024x1024x64. CTA = 128 q-rows, 128 threads,
// KV block 32, 2-stage cp.async, 3 CTAs/SM (smem 36.9KB, reg cap 170).
// S-phase frags via ldmatrix.x4; P stays in registers; V via ldmatrix.trans.
// ---------------------------------------------------------------------------
#define ASTR 72                      // Q/K/V row stride in halves (144 B)
#define AQ_H   (128 * ASTR)          // 9216
#define AK_H   (32 * ASTR)           // 2304
#define AV_H   (32 * ASTR)           // 2304
#define ATT_SMEM_B ((AQ_H + 2 * AK_H + 2 * AV_H) * 2)   // 36864 B

__global__ __launch_bounds__(128, 3) void attn_k() {
    extern __shared__ __half smh[];
    const uint32_t smb = smem_u32(smh);

    const int tid = threadIdx.x, lane = tid & 31, wid = tid >> 5;
    const int lr = lane >> 2, lc = lane & 3;
    const int qb = blockIdx.x, tbh = blockIdx.y;
    const __half* qp = g_q + (size_t)tbh * NSEQ * DHD + (size_t)qb * 128 * DHD;
    const __half* kp = g_k + (size_t)tbh * NSEQ * DHD;
    const __half* vp = g_v + (size_t)tbh * NSEQ * DHD;

    const int m8 = lane >> 3, rr = lane & 7;
    const int a_row = ((m8 & 1) << 3) + rr;
    const int a_col = (m8 >> 1) << 3;
    const int b_row = ((m8 >> 1) << 3) + rr;
    const int b_col = (m8 & 1) << 3;

    // prefetch KV stage: K 256 + V 256 chunks of 16B, 2+2 per thread
    auto prefetch_kv = [&](int s, int kvb) {
        const uint32_t kb = smb + (uint32_t)(AQ_H + s * AK_H) * 2u;
        const uint32_t vb = smb + (uint32_t)(AQ_H + 2 * AK_H + s * AV_H) * 2u;
        const __half* kg = kp + (size_t)kvb * 32 * DHD;
        const __half* vg = vp + (size_t)kvb * 32 * DHD;
#pragma unroll
        for (int u = tid; u < 256; u += 128) {
            const int row = u >> 3, c = (u & 7) << 3;
            cp16(kb + (uint32_t)(row * ASTR + c) * 2u, kg + row * DHD + c);
        }
#pragma unroll
        for (int u = tid; u < 256; u += 128) {
            const int row = u >> 3, c = (u & 7) << 3;
            cp16(vb + (uint32_t)(row * ASTR + c) * 2u, vg + row * DHD + c);
        }
    };

    // Q load (once, 128x64 halves = 1024 chunks) + first KV stage
#pragma unroll
    for (int u = tid; u < 1024; u += 128) {
        const int row = u >> 3, c = (u & 7) << 3;
        cp16(smb + (uint32_t)(row * ASTR + c) * 2u, qp + row * DHD + c);
    }
    prefetch_kv(0, 0);
    CP_COMMIT();

    float ctx[2][8][4];
#pragma unroll
    for (int i = 0; i < 2; i++)
#pragma unroll
        for (int j = 0; j < 8; j++)
#pragma unroll
            for (int e = 0; e < 4; e++) ctx[i][j][e] = 0.f;
    float rs[2][2] = {{0.f, 0.f}, {0.f, 0.f}};

    const int wm = wid * 32;
    const uint32_t kstage[2] = {
        smb + (uint32_t)AQ_H * 2u,
        smb + (uint32_t)(AQ_H + AK_H) * 2u
    };
    const uint32_t vstage[2] = {
        smb + (uint32_t)(AQ_H + 2 * AK_H) * 2u,
        smb + (uint32_t)(AQ_H + 2 * AK_H + AV_H) * 2u
    };

    for (int kvb = 0; kvb < NSEQ / 32; kvb++) {
        const int s = kvb & 1;
        if (kvb + 1 < NSEQ / 32) {
            prefetch_kv(s ^ 1, kvb + 1);
            CP_COMMIT();
            CP_WAIT(1);
        } else {
            CP_WAIT(0);
        }
        __syncthreads();

        // S = q_s @ k^T (warp: 32 q-rows x 32 keys), k-dim = dh 64 = 4 x k16
        float sacc[2][4][4];
#pragma unroll
        for (int i = 0; i < 2; i++)
#pragma unroll
            for (int j = 0; j < 4; j++)
#pragma unroll
                for (int e = 0; e < 4; e++) sacc[i][j][e] = 0.f;

#pragma unroll
        for (int ks = 0; ks < 4; ks++) {
            const int kb = ks * 16;
            unsigned af[2][4];
#pragma unroll
            for (int mi = 0; mi < 2; mi++)
                ldmx4(af[mi][0], af[mi][1], af[mi][2], af[mi][3],
                      smb + (uint32_t)((wm + mi * 16 + a_row) * ASTR + kb + a_col) * 2u);
            unsigned bf[4][2];
#pragma unroll
            for (int ni2 = 0; ni2 < 2; ni2++)
                ldmx4(bf[2 * ni2][0], bf[2 * ni2][1], bf[2 * ni2 + 1][0], bf[2 * ni2 + 1][1],
                      kstage[s] + (uint32_t)((ni2 * 16 + b_row) * ASTR + kb + b_col) * 2u);
#pragma unroll
            for (int mi = 0; mi < 2; mi++)
#pragma unroll
                for (int ni = 0; ni < 4; ni++)
                    mma16(sacc[mi][ni][0], sacc[mi][ni][1], sacc[mi][ni][2], sacc[mi][ni][3],
                          af[mi][0], af[mi][1], af[mi][2], af[mi][3],
                          bf[ni][0], bf[ni][1]);
        }

        // relu in place + rowsum (fp32)
#pragma unroll
        for (int mi = 0; mi < 2; mi++)
#pragma unroll
            for (int ni = 0; ni < 4; ni++) {
                float p0 = fmaxf(sacc[mi][ni][0], 0.f);
                float p1 = fmaxf(sacc[mi][ni][1], 0.f);
                float p2 = fmaxf(sacc[mi][ni][2], 0.f);
                float p3 = fmaxf(sacc[mi][ni][3], 0.f);
                sacc[mi][ni][0] = p0; sacc[mi][ni][1] = p1;
                sacc[mi][ni][2] = p2; sacc[mi][ni][3] = p3;
                rs[mi][0] += p0 + p1;
                rs[mi][1] += p2 + p3;
            }

        // ctx += P @ V ; P fragments built from sacc registers (layout match)
#pragma unroll
        for (int ks = 0; ks < 2; ks++) {
            unsigned af[2][4];
#pragma unroll
            for (int mi = 0; mi < 2; mi++) {
                af[mi][0] = packh2(sacc[mi][2 * ks][0],     sacc[mi][2 * ks][1]);
                af[mi][1] = packh2(sacc[mi][2 * ks][2],     sacc[mi][2 * ks][3]);
                af[mi][2] = packh2(sacc[mi][2 * ks + 1][0], sacc[mi][2 * ks + 1][1]);
                af[mi][3] = packh2(sacc[mi][2 * ks + 1][2], sacc[mi][2 * ks + 1][3]);
            }
            unsigned bf[8][2];
            const int vkey = ks * 16 + (lane & 15);
            const int vcol8 = (lane >> 4) << 3;
#pragma unroll
            for (int ni2 = 0; ni2 < 4; ni2++) {
                const uint32_t addr = vstage[s] +
                    (uint32_t)(vkey * ASTR + ni2 * 16 + vcol8) * 2u;
                ldmx4t(bf[2 * ni2][0], bf[2 * ni2][1],
                       bf[2 * ni2 + 1][0], bf[2 * ni2 + 1][1], addr);
            }
#pragma unroll
            for (int mi = 0; mi < 2; mi++)
#pragma unroll
                for (int ni = 0; ni < 8; ni++)
                    mma16(ctx[mi][ni][0], ctx[mi][ni][1], ctx[mi][ni][2], ctx[mi][ni][3],
                          af[mi][0], af[mi][1], af[mi][2], af[mi][3],
                          bf[ni][0], bf[ni][1]);
        }
        __syncthreads();
    }

    // finalize rowsums (reduce across the 4 lanes sharing a row)
    float inv[2][2];
#pragma unroll
    for (int mi = 0; mi < 2; mi++)
#pragma unroll
        for (int hh = 0; hh < 2; hh++) {
            float r = rs[mi][hh];
            r += __shfl_xor_sync(0xffffffffu, r, 1);
            r += __shfl_xor_sync(0xffffffffu, r, 2);
            inv[mi][hh] = 1.f / (r + 1e-6f);
        }

    // write merged ctx [s, h*64+d] as fp16 (feeds out-proj GEMM)
    const int tb = tbh / NH, h = tbh % NH;
#pragma unroll
    for (int mi = 0; mi < 2; mi++)
#pragma unroll
        for (int ni = 0; ni < 8; ni++)
#pragma unroll
            for (int eh = 0; eh < 2; eh++) {
                const int qrow = qb * 128 + wm + mi * 16 + lr + (eh << 3);
                const int sidx = tb * NSEQ + qrow;
                const int c = h * DHD + ni * 8 + (lc << 1);
                const float iv = inv[mi][eh];
                *reinterpret_cast<__half2*>(&g_ctx[(size_t)sidx * DM + c]) =
                    __floats2half2_rn(ctx[mi][ni][eh * 2] * iv,
                                      ctx[mi][ni][eh * 2 + 1] * iv);
            }
}

// ---------------------------------------------------------------------------
// Launch
// ---------------------------------------------------------------------------
extern "C" void kernel_launch(void* const* d_in, const int* in_sizes, int n_in,
                              void* d_out, int out_size) {
    const float* x  = (const float*)d_in[0];
    const float* Wq = (const float*)d_in[1];
    const float* bq = (const float*)d_in[2];
    const float* Wk = (const float*)d_in[3];
    const float* bk = (const float*)d_in[4];
    const float* Wv = (const float*)d_in[5];
    const float* bv = (const float*)d_in[6];
    const float* Wo = (const float*)d_in[7];
    const float* bo = (const float*)d_in[8];
    float* out = (float*)d_out;

    (void)in_sizes; (void)n_in; (void)out_size;

    cudaFuncSetAttribute(gemm_qkv_k, cudaFuncAttributeMaxDynamicSharedMemorySize, GSMEM_B);
    cudaFuncSetAttribute(gemm_out_k, cudaFuncAttributeMaxDynamicSharedMemorySize, GSMEM_B);
    cudaFuncSetAttribute(attn_k, cudaFuncAttributeMaxDynamicSharedMemorySize, ATT_SMEM_B);

    // fused fp16 pre-convert (x + 4 weights, one launch)
    cvt_all_k<<<(NCVT4 + 255) / 256, 256>>>(x, Wq, Wk, Wv, Wo);

    // q/k/v projections (CTA 128x128, 8 warps of 64x32, 2 CTAs/SM)
    gemm_qkv_k<<<dim3(NS / GBM, DM / GBN, 3), 256, GSMEM_B>>>(bq, bk, bv);

    // spike attention
    attn_k<<<dim3(NSEQ / 128, NTB * NH), 128, ATT_SMEM_B>>>();

    // output projection
    gemm_out_k<<<dim3(NS / GBM, DM / GBN), 256, GSMEM_B>>>(bo, out);
}

// round 17
// speedup vs baseline: 1.5340x; 1.5340x over previous
#include <cuda_runtime.h>
#include <cuda_fp16.h>
#include <cstdint>

#define NH   12
#define DHD  64
#define NSEQ 1024
#define DM   768
#define NTB  16
#define NS   16384   // NTB * NSEQ tokens

// ---------------------------------------------------------------------------
// Scratch (static device globals; no runtime allocation allowed)
// ---------------------------------------------------------------------------
__device__ __align__(256) __half g_q[(size_t)NTB * NH * NSEQ * DHD];   // h(0.125*q)
__device__ __align__(256) __half g_k[(size_t)NTB * NH * NSEQ * DHD];   // h(k)
__device__ __align__(256) __half g_v[(size_t)NTB * NH * NSEQ * DHD];   // h(v)
__device__ __align__(256) __half g_ctx[(size_t)NS * DM];               // h(ctx)
__device__ __align__(256) __half g_xc[(size_t)NS * DM];                // h(x)
__device__ __align__(256) __half g_wqc[(size_t)DM * DM];
__device__ __align__(256) __half g_wkc[(size_t)DM * DM];
__device__ __align__(256) __half g_wvc[(size_t)DM * DM];
__device__ __align__(256) __half g_woc[(size_t)DM * DM];

// ---------------------------------------------------------------------------
// Helpers
// ---------------------------------------------------------------------------
__device__ __forceinline__ uint32_t smem_u32(const void* p) {
    uint32_t a;
    asm("{ .reg .u64 t; cvta.to.shared.u64 t, %1; cvt.u32.u64 %0, t; }" : "=r"(a) : "l"(p));
    return a;
}

__device__ __forceinline__ void cp16(uint32_t dst, const void* src) {
    asm volatile("cp.async.cg.shared.global [%0], [%1], 16;" :: "r"(dst), "l"(src) : "memory");
}
#define CP_COMMIT() asm volatile("cp.async.commit_group;" ::: "memory")
#define CP_WAIT(n)  asm volatile("cp.async.wait_group %0;" :: "n"(n) : "memory")

// fp16 MMA, fp32 accumulate: D(16x8) += A(16x16) * B(16x8)
__device__ __forceinline__ void mma16(float& c0, float& c1, float& c2, float& c3,
                                      unsigned a0, unsigned a1, unsigned a2, unsigned a3,
                                      unsigned b0, unsigned b1) {
    asm volatile(
        "mma.sync.aligned.m16n8k16.row.col.f32.f16.f16.f32 "
        "{%0,%1,%2,%3},{%4,%5,%6,%7},{%8,%9},{%0,%1,%2,%3};"
        : "+f"(c0), "+f"(c1), "+f"(c2), "+f"(c3)
        : "r"(a0), "r"(a1), "r"(a2), "r"(a3), "r"(b0), "r"(b1));
}

// ldmatrix x4 (non-trans / trans) b16
__device__ __forceinline__ void ldmx4(unsigned& r0, unsigned& r1, unsigned& r2, unsigned& r3,
                                      uint32_t addr) {
    asm volatile("ldmatrix.sync.aligned.m8n8.x4.shared.b16 {%0,%1,%2,%3}, [%4];"
                 : "=r"(r0), "=r"(r1), "=r"(r2), "=r"(r3) : "r"(addr));
}
__device__ __forceinline__ void ldmx4t(unsigned& r0, unsigned& r1, unsigned& r2, unsigned& r3,
                                       uint32_t addr) {
    asm volatile("ldmatrix.sync.aligned.m8n8.x4.trans.shared.b16 {%0,%1,%2,%3}, [%4];"
                 : "=r"(r0), "=r"(r1), "=r"(r2), "=r"(r3) : "r"(addr));
}

__device__ __forceinline__ unsigned packh2(float a, float b) {
    __half2 h = __floats2half2_rn(a, b);
    return *reinterpret_cast<unsigned*>(&h);
}

// ---------------------------------------------------------------------------
// Fused fp16 pre-convert: one launch covers x + the 4 weight matrices
// ---------------------------------------------------------------------------
#define NX4 ((NS * DM) / 4)
#define NW4 ((DM * DM) / 4)
#define NCVT4 (NX4 + 4 * NW4)

__global__ __launch_bounds__(256) void cvt_all_k(const float* __restrict__ x,
                                                 const float* __restrict__ Wq,
                                                 const float* __restrict__ Wk,
                                                 const float* __restrict__ Wv,
                                                 const float* __restrict__ Wo) {
    int i = blockIdx.x * blockDim.x + threadIdx.x;
    if (i >= NCVT4) return;
    const float* s;
    __half* d;
    int j;
    if (i < NX4) { s = x; d = g_xc; j = i; }
    else {
        j = i - NX4;
        const int w = j / NW4;
        j -= w * NW4;
        s = (w == 0) ? Wq : (w == 1) ? Wk : (w == 2) ? Wv : Wo;
        d = (w == 0) ? g_wqc : (w == 1) ? g_wkc : (w == 2) ? g_wvc : g_woc;
    }
    float4 v = reinterpret_cast<const float4*>(s)[j];
    __half2 h0 = __floats2half2_rn(v.x, v.y);
    __half2 h1 = __floats2half2_rn(v.z, v.w);
    uint2 pk;
    pk.x = *reinterpret_cast<unsigned*>(&h0);
    pk.y = *reinterpret_cast<unsigned*>(&h1);
    reinterpret_cast<uint2*>(d)[j] = pk;
}

// ---------------------------------------------------------------------------
// fp16 HMMA GEMM: out[s,c] = sum_k A[s,k]*W[c,k] + bias[c]
// CTA 128x128, 128 thr = 4 warps (2m x 2n), warp tile 64x64 (R15 shape —
// R16 proved shrinking it floods the LDS pipe).  BK=64, THREE-stage cp.async
// ring: stage load gets a 2-compute-phase latency budget (R15's 2-stage gave
// only 1 phase and was exposed-latency bound: nothing saturated in ncu).
// CP_WAIT(1) mid-loop, CP_WAIT(0) on the last iteration.
// mode: 0 = head-split q (x0.125), 1 = head-split k/v, 2 = flat fp32 out
// ---------------------------------------------------------------------------
#define GBM 128
#define GBN 128
#define GSTR 72
#define GA_H (GBM * GSTR)                   // 9216 halves
#define GSTG_H (2 * GA_H)                   // 18432 halves (A + B)
#define GNST 3
#define GSMEM_B (GNST * GSTG_H * 2)         // 110592 bytes
#define GKIT (DM / 64)                      // 12

__device__ __forceinline__ void gemm_body(const __half* __restrict__ A,
                                          const __half* __restrict__ W,
                                          const float* __restrict__ bias,
                                          void* __restrict__ dstp, int mode) {
    extern __shared__ __half smh[];
    const uint32_t smb = smem_u32(smh);
    const int tid  = threadIdx.x;
    const int lane = tid & 31, wid = tid >> 5;
    const int wm = (wid & 1) * 64;
    const int wn = (wid >> 1) * 64;
    const int row0 = blockIdx.x * GBM, col0 = blockIdx.y * GBN;
    const int lr = lane >> 2, lc = lane & 3;

    // ldmatrix lane-address components
    const int m8 = lane >> 3, rr = lane & 7;
    const int a_row = ((m8 & 1) << 3) + rr;   // A: row offset, col += ((m8>>1)<<3)
    const int a_col = (m8 >> 1) << 3;
    const int b_row = ((m8 >> 1) << 3) + rr;  // B: n-row offset, col += ((m8&1)<<3)
    const int b_col = (m8 & 1) << 3;

    float acc[4][8][4];
#pragma unroll
    for (int i = 0; i < 4; i++)
#pragma unroll
        for (int j = 0; j < 8; j++)
#pragma unroll
            for (int e = 0; e < 4; e++) acc[i][j][e] = 0.f;

    // prefetch one stage: A 1024 + B 1024 chunks of 16B (8 halves), 8+8/thr
    auto prefetch = [&](int s, int kk) {
        const uint32_t ab = smb + (uint32_t)(s * GSTG_H) * 2u;
        const uint32_t bb = ab + (uint32_t)GA_H * 2u;
#pragma unroll
        for (int u = tid; u < 1024; u += 128) {
            const int row = u >> 3, c = (u & 7) << 3;
            cp16(ab + (uint32_t)(row * GSTR + c) * 2u,
                 A + (size_t)(row0 + row) * DM + kk + c);
        }
#pragma unroll
        for (int u = tid; u < 1024; u += 128) {
            const int row = u >> 3, c = (u & 7) << 3;
            cp16(bb + (uint32_t)(row * GSTR + c) * 2u,
                 W + (size_t)(col0 + row) * DM + kk + c);
        }
    };

    prefetch(0, 0);
    CP_COMMIT();
    prefetch(1, 64);
    CP_COMMIT();

    int s = 0, ps = 2;   // compute stage / prefetch stage
    for (int it = 0; it < GKIT; it++) {
        if (it + 1 < GKIT) { CP_WAIT(1); } else { CP_WAIT(0); }
        __syncthreads();
        if (it + 2 < GKIT) {
            prefetch(ps, (it + 2) * 64);
            CP_COMMIT();
        }

        const uint32_t abase = smb + (uint32_t)(s * GSTG_H) * 2u;
        const uint32_t bbase = abase + (uint32_t)GA_H * 2u;
#pragma unroll
        for (int ks = 0; ks < 4; ks++) {
            const int kb = ks * 16;
            unsigned af[4][4];
#pragma unroll
            for (int mi = 0; mi < 4; mi++)
                ldmx4(af[mi][0], af[mi][1], af[mi][2], af[mi][3],
                      abase + (uint32_t)((wm + mi * 16 + a_row) * GSTR + kb + a_col) * 2u);
            unsigned bf[8][2];
#pragma unroll
            for (int ni2 = 0; ni2 < 4; ni2++)
                ldmx4(bf[2 * ni2][0], bf[2 * ni2][1], bf[2 * ni2 + 1][0], bf[2 * ni2 + 1][1],
                      bbase + (uint32_t)((wn + ni2 * 16 + b_row) * GSTR + kb + b_col) * 2u);
#pragma unroll
            for (int mi = 0; mi < 4; mi++)
#pragma unroll
                for (int ni = 0; ni < 8; ni++)
                    mma16(acc[mi][ni][0], acc[mi][ni][1], acc[mi][ni][2], acc[mi][ni][3],
                          af[mi][0], af[mi][1], af[mi][2], af[mi][3],
                          bf[ni][0], bf[ni][1]);
        }
        s = (s == GNST - 1) ? 0 : s + 1;
        ps = (ps == GNST - 1) ? 0 : ps + 1;
    }

    // epilogue
#pragma unroll
    for (int mi = 0; mi < 4; mi++)
#pragma unroll
        for (int ni = 0; ni < 8; ni++)
#pragma unroll
            for (int eh = 0; eh < 2; eh++) {
                const int gr = row0 + wm + mi * 16 + lr + (eh << 3);
                const int gc = col0 + wn + ni * 8 + (lc << 1);
                float v0 = acc[mi][ni][eh * 2]     + __ldg(bias + gc);
                float v1 = acc[mi][ni][eh * 2 + 1] + __ldg(bias + gc + 1);
                if (mode == 2) {
                    float* dst = (float*)dstp;
                    *reinterpret_cast<float2*>(dst + (size_t)gr * DM + gc) =
                        make_float2(v0, v1);
                } else {
                    if (mode == 0) { v0 *= 0.125f; v1 *= 0.125f; }
                    __half* dst = (__half*)dstp;
                    const int tb = gr >> 10, n = gr & 1023;
                    const int h = gc >> 6, d = gc & 63;
                    __half2 hv = __floats2half2_rn(v0, v1);
                    *reinterpret_cast<__half2*>(
                        dst + (((size_t)(tb * NH + h)) * NSEQ + n) * DHD + d) = hv;
                }
            }
}

__global__ __launch_bounds__(128) void gemm_qkv_k(const float* __restrict__ bq,
                                                  const float* __restrict__ bk,
                                                  const float* __restrict__ bv) {
    const int z = blockIdx.z;
    const __half* W = (z == 0) ? g_wqc : (z == 1) ? g_wkc : g_wvc;
    const float* b = (z == 0) ? bq : (z == 1) ? bk : bv;
    __half* dst = (z == 0) ? g_q : (z == 1) ? g_k : g_v;
    gemm_body(g_xc, W, b, dst, (z == 0) ? 0 : 1);
}

__global__ __launch_bounds__(128) void gemm_out_k(const float* __restrict__ bo,
                                                  float* __restrict__ out) {
    gemm_body(g_ctx, g_woc, bo, out, 2);
}

// ---------------------------------------------------------------------------
// Attention (fp16, exact R15 385.4us version): per (tb,h), 1024x1024x64.
// CTA = 128 q-rows, 128 threads, KV block 32, 2-stage cp.async, 2 CTAs/SM.
// S-phase frags via ldmatrix.x4; P stays in registers; V via ldmatrix.trans.
// NO reg cap beyond (128,2): R16 proved capping below natural usage spills.
// ---------------------------------------------------------------------------
#define ASTR 72                      // Q/K/V row stride in halves (144 B)
#define AQ_H   (128 * ASTR)          // 9216
#define AK_H   (32 * ASTR)           // 2304
#define AV_H   (32 * ASTR)           // 2304
#define ATT_SMEM_B ((AQ_H + 2 * AK_H + 2 * AV_H) * 2)   // 36864 B

__global__ __launch_bounds__(128, 2) void attn_k() {
    extern __shared__ __half smh[];
    const uint32_t smb = smem_u32(smh);

    const int tid = threadIdx.x, lane = tid & 31, wid = tid >> 5;
    const int lr = lane >> 2, lc = lane & 3;
    const int qb = blockIdx.x, tbh = blockIdx.y;
    const __half* qp = g_q + (size_t)tbh * NSEQ * DHD + (size_t)qb * 128 * DHD;
    const __half* kp = g_k + (size_t)tbh * NSEQ * DHD;
    const __half* vp = g_v + (size_t)tbh * NSEQ * DHD;

    const int m8 = lane >> 3, rr = lane & 7;
    const int a_row = ((m8 & 1) << 3) + rr;
    const int a_col = (m8 >> 1) << 3;
    const int b_row = ((m8 >> 1) << 3) + rr;
    const int b_col = (m8 & 1) << 3;

    // prefetch KV stage: K 256 + V 256 chunks of 16B, 2+2 per thread
    auto prefetch_kv = [&](int s, int kvb) {
        const uint32_t kb = smb + (uint32_t)(AQ_H + s * AK_H) * 2u;
        const uint32_t vb = smb + (uint32_t)(AQ_H + 2 * AK_H + s * AV_H) * 2u;
        const __half* kg = kp + (size_t)kvb * 32 * DHD;
        const __half* vg = vp + (size_t)kvb * 32 * DHD;
#pragma unroll
        for (int u = tid; u < 256; u += 128) {
            const int row = u >> 3, c = (u & 7) << 3;
            cp16(kb + (uint32_t)(row * ASTR + c) * 2u, kg + row * DHD + c);
        }
#pragma unroll
        for (int u = tid; u < 256; u += 128) {
            const int row = u >> 3, c = (u & 7) << 3;
            cp16(vb + (uint32_t)(row * ASTR + c) * 2u, vg + row * DHD + c);
        }
    };

    // Q load (once, 128x64 halves = 1024 chunks) + first KV stage
#pragma unroll
    for (int u = tid; u < 1024; u += 128) {
        const int row = u >> 3, c = (u & 7) << 3;
        cp16(smb + (uint32_t)(row * ASTR + c) * 2u, qp + row * DHD + c);
    }
    prefetch_kv(0, 0);
    CP_COMMIT();

    float ctx[2][8][4];
#pragma unroll
    for (int i = 0; i < 2; i++)
#pragma unroll
        for (int j = 0; j < 8; j++)
#pragma unroll
            for (int e = 0; e < 4; e++) ctx[i][j][e] = 0.f;
    float rs[2][2] = {{0.f, 0.f}, {0.f, 0.f}};

    const int wm = wid * 32;
    const uint32_t kstage[2] = {
        smb + (uint32_t)AQ_H * 2u,
        smb + (uint32_t)(AQ_H + AK_H) * 2u
    };
    const uint32_t vstage[2] = {
        smb + (uint32_t)(AQ_H + 2 * AK_H) * 2u,
        smb + (uint32_t)(AQ_H + 2 * AK_H + AV_H) * 2u
    };

    for (int kvb = 0; kvb < NSEQ / 32; kvb++) {
        const int s = kvb & 1;
        if (kvb + 1 < NSEQ / 32) {
            prefetch_kv(s ^ 1, kvb + 1);
            CP_COMMIT();
            CP_WAIT(1);
        } else {
            CP_WAIT(0);
        }
        __syncthreads();

        // S = q_s @ k^T (warp: 32 q-rows x 32 keys), k-dim = dh 64 = 4 x k16
        float sacc[2][4][4];
#pragma unroll
        for (int i = 0; i < 2; i++)
#pragma unroll
            for (int j = 0; j < 4; j++)
#pragma unroll
                for (int e = 0; e < 4; e++) sacc[i][j][e] = 0.f;

#pragma unroll
        for (int ks = 0; ks < 4; ks++) {
            const int kb = ks * 16;
            unsigned af[2][4];
#pragma unroll
            for (int mi = 0; mi < 2; mi++)
                ldmx4(af[mi][0], af[mi][1], af[mi][2], af[mi][3],
                      smb + (uint32_t)((wm + mi * 16 + a_row) * ASTR + kb + a_col) * 2u);
            unsigned bf[4][2];
#pragma unroll
            for (int ni2 = 0; ni2 < 2; ni2++)
                ldmx4(bf[2 * ni2][0], bf[2 * ni2][1], bf[2 * ni2 + 1][0], bf[2 * ni2 + 1][1],
                      kstage[s] + (uint32_t)((ni2 * 16 + b_row) * ASTR + kb + b_col) * 2u);
#pragma unroll
            for (int mi = 0; mi < 2; mi++)
#pragma unroll
                for (int ni = 0; ni < 4; ni++)
                    mma16(sacc[mi][ni][0], sacc[mi][ni][1], sacc[mi][ni][2], sacc[mi][ni][3],
                          af[mi][0], af[mi][1], af[mi][2], af[mi][3],
                          bf[ni][0], bf[ni][1]);
        }

        // relu in place + rowsum (fp32)
#pragma unroll
        for (int mi = 0; mi < 2; mi++)
#pragma unroll
            for (int ni = 0; ni < 4; ni++) {
                float p0 = fmaxf(sacc[mi][ni][0], 0.f);
                float p1 = fmaxf(sacc[mi][ni][1], 0.f);
                float p2 = fmaxf(sacc[mi][ni][2], 0.f);
                float p3 = fmaxf(sacc[mi][ni][3], 0.f);
                sacc[mi][ni][0] = p0; sacc[mi][ni][1] = p1;
                sacc[mi][ni][2] = p2; sacc[mi][ni][3] = p3;
                rs[mi][0] += p0 + p1;
                rs[mi][1] += p2 + p3;
            }

        // ctx += P @ V ; P fragments built from sacc registers (layout match)
#pragma unroll
        for (int ks = 0; ks < 2; ks++) {
            unsigned af[2][4];
#pragma unroll
            for (int mi = 0; mi < 2; mi++) {
                af[mi][0] = packh2(sacc[mi][2 * ks][0],     sacc[mi][2 * ks][1]);
                af[mi][1] = packh2(sacc[mi][2 * ks][2],     sacc[mi][2 * ks][3]);
                af[mi][2] = packh2(sacc[mi][2 * ks + 1][0], sacc[mi][2 * ks + 1][1]);
                af[mi][3] = packh2(sacc[mi][2 * ks + 1][2], sacc[mi][2 * ks + 1][3]);
            }
            unsigned bf[8][2];
            const int vkey = ks * 16 + (lane & 15);
            const int vcol8 = (lane >> 4) << 3;
#pragma unroll
            for (int ni2 = 0; ni2 < 4; ni2++) {
                const uint32_t addr = vstage[s] +
                    (uint32_t)(vkey * ASTR + ni2 * 16 + vcol8) * 2u;
                ldmx4t(bf[2 * ni2][0], bf[2 * ni2][1],
                       bf[2 * ni2 + 1][0], bf[2 * ni2 + 1][1], addr);
            }
#pragma unroll
            for (int mi = 0; mi < 2; mi++)
#pragma unroll
                for (int ni = 0; ni < 8; ni++)
                    mma16(ctx[mi][ni][0], ctx[mi][ni][1], ctx[mi][ni][2], ctx[mi][ni][3],
                          af[mi][0], af[mi][1], af[mi][2], af[mi][3],
                          bf[ni][0], bf[ni][1]);
        }
        __syncthreads();
    }

    // finalize rowsums (reduce across the 4 lanes sharing a row)
    float inv[2][2];
#pragma unroll
    for (int mi = 0; mi < 2; mi++)
#pragma unroll
        for (int hh = 0; hh < 2; hh++) {
            float r = rs[mi][hh];
            r += __shfl_xor_sync(0xffffffffu, r, 1);
            r += __shfl_xor_sync(0xffffffffu, r, 2);
            inv[mi][hh] = 1.f / (r + 1e-6f);
        }

    // write merged ctx [s, h*64+d] as fp16 (feeds out-proj GEMM)
    const int tb = tbh / NH, h = tbh % NH;
#pragma unroll
    for (int mi = 0; mi < 2; mi++)
#pragma unroll
        for (int ni = 0; ni < 8; ni++)
#pragma unroll
            for (int eh = 0; eh < 2; eh++) {
                const int qrow = qb * 128 + wm + mi * 16 + lr + (eh << 3);
                const int sidx = tb * NSEQ + qrow;
                const int c = h * DHD + ni * 8 + (lc << 1);
                const float iv = inv[mi][eh];
                *reinterpret_cast<__half2*>(&g_ctx[(size_t)sidx * DM + c]) =
                    __floats2half2_rn(ctx[mi][ni][eh * 2] * iv,
                                      ctx[mi][ni][eh * 2 + 1] * iv);
            }
}

// ---------------------------------------------------------------------------
// Launch
// ---------------------------------------------------------------------------
extern "C" void kernel_launch(void* const* d_in, const int* in_sizes, int n_in,
                              void* d_out, int out_size) {
    const float* x  = (const float*)d_in[0];
    const float* Wq = (const float*)d_in[1];
    const float* bq = (const float*)d_in[2];
    const float* Wk = (const float*)d_in[3];
    const float* bk = (const float*)d_in[4];
    const float* Wv = (const float*)d_in[5];
    const float* bv = (const float*)d_in[6];
    const float* Wo = (const float*)d_in[7];
    const float* bo = (const float*)d_in[8];
    float* out = (float*)d_out;

    (void)in_sizes; (void)n_in; (void)out_size;

    cudaFuncSetAttribute(gemm_qkv_k, cudaFuncAttributeMaxDynamicSharedMemorySize, GSMEM_B);
    cudaFuncSetAttribute(gemm_out_k, cudaFuncAttributeMaxDynamicSharedMemorySize, GSMEM_B);
    cudaFuncSetAttribute(attn_k, cudaFuncAttributeMaxDynamicSharedMemorySize, ATT_SMEM_B);

    // fused fp16 pre-convert (x + 4 weights, one launch)
    cvt_all_k<<<(NCVT4 + 255) / 256, 256>>>(x, Wq, Wk, Wv, Wo);

    // q/k/v projections (CTA 128x128, 4 warps of 64x64, 3-stage pipeline)
    gemm_qkv_k<<<dim3(NS / GBM, DM / GBN, 3), 128, GSMEM_B>>>(bq, bk, bv);

    // spike attention (R15 config)
    attn_k<<<dim3(NSEQ / 128, NTB * NH), 128, ATT_SMEM_B>>>();

    // output projection
    gemm_out_k<<<dim3(NS / GBM, DM / GBN), 128, GSMEM_B>>>(bo, out);
}